// round 8
// baseline (speedup 1.0000x reference)
#include <cuda_runtime.h>
#include <stdint.h>

// MinusSpan: B=16, T=2048, D=1024 (H=512), N_SPANS=256
// out[b,s] = concat(fwd[j]-f_pre, bwd[i]-b_post, f_pre, b_post), zeroed if i==0&&j==0
// f_pre = fwd[i-1] if i>=1 else 0 ; b_post = bwd[j+1] if j+1<T else 0

static constexpr int Bc = 16;
static constexpr int Tc = 2048;
static constexpr int Dc = 1024;
static constexpr int NS = 256;
static constexpr int D4 = Dc / 4;           // 256 float4 per (b,t) row
static constexpr int H4 = Dc / 8;           // 128 float4 per half-row
static constexpr int NSPAN_TOT = Bc * NS;   // 4096 spans
static constexpr int NSP = 2;               // spans per CTA

__device__ __forceinline__ void l2_prefetch(const float4* p) {
    asm volatile("prefetch.global.L2 [%0];" :: "l"(p));
}

__global__ __launch_bounds__(128)   // same cap as the 10.75us R5 winner (regs=32)
void minus_span_kernel(const float* __restrict__ inp,
                       const unsigned int* __restrict__ idxw,  // raw 32-bit view of span_idxs
                       float* __restrict__ out)
{
    const int t    = threadIdx.x;           // 0..127 (one float4 per region)
    const int lane = t & 31;

    // ---- per-warp index-dtype detection (no extra kernel launch) ----
    // int64 buffer (values < 2048, little-endian): every odd 32-bit word is a
    // zero high half. int32 buffer: odd words are random j in [0,2048) —
    // P(all 64 samples zero) ~ 0. Both layouts have >= 8192 words.
    unsigned w0 = __ldg(&idxw[2 * lane + 1]);
    unsigned w1 = __ldg(&idxw[2 * (lane + 32) + 1]);
    const bool is64 = (__ballot_sync(0xffffffffu, (w0 | w1) != 0u) == 0u);

    const int span0 = blockIdx.x * NSP;
    const float4* __restrict__ f4 = reinterpret_cast<const float4*>(inp);
    const float4 zero = make_float4(0.f, 0.f, 0.f, 0.f);

    // Per-span state: 32-bit element offsets (max offset 8.4M < 2^31)
    unsigned ofe[NSP], obs[NSP], ofp[NSP], obp[NSP];
    bool skip[NSP], hpre[NSP], hpost[NSP];

    #pragma unroll
    for (int s = 0; s < NSP; s++) {
        const int span = span0 + s;
        const int b    = span >> 8;         // span / NS

        // Index values fit in the low 32-bit word under both layouts.
        int i, j;
        if (is64) {
            i = (int)idxw[4 * span + 0];
            j = (int)idxw[4 * span + 2];
        } else {
            i = (int)idxw[2 * span + 0];
            j = (int)idxw[2 * span + 1];
        }

        skip[s]  = (i == 0) && (j == 0);
        hpre[s]  = !skip[s] && (i >= 1);
        hpost[s] = !skip[s] && (j + 1 < Tc);

        // Safety clamp: garbage indices become wrong values, never faults.
        int ic = min(max(i, 0), Tc - 1);
        int jc = min(max(j, 0), Tc - 1);
        int ip = (ic >= 1) ? ic - 1 : 0;
        int jn = (jc + 1 < Tc) ? jc + 1 : Tc - 1;

        const unsigned base = (unsigned)b * (Tc * D4);
        ofe[s] = base + (unsigned)jc * D4 + t;        // fwd[j]
        obs[s] = base + (unsigned)ic * D4 + H4 + t;   // bwd[i]
        ofp[s] = base + (unsigned)ip * D4 + t;        // fwd[i-1]
        obp[s] = base + (unsigned)jn * D4 + H4 + t;   // bwd[j+1]

        // Fire prefetches the moment each span's offsets exist: true MLP=8
        // per thread with ZERO destination-register cost. The later real
        // loads then hit L2 (~240cyc) instead of DRAM (~600cyc).
        l2_prefetch(&f4[ofe[s]]);
        l2_prefetch(&f4[obs[s]]);
        l2_prefetch(&f4[ofp[s]]);
        l2_prefetch(&f4[obp[s]]);
    }

    // ---- real loads (mostly L2 hits now); register budget same as R5 ----
    float4 fe[NSP], bs[NSP], fp[NSP], bp[NSP];
    #pragma unroll
    for (int s = 0; s < NSP; s++) {
        fe[s] = skip[s]  ? zero : __ldg(&f4[ofe[s]]);
        bs[s] = skip[s]  ? zero : __ldg(&f4[obs[s]]);
        fp[s] = hpre[s]  ? __ldg(&f4[ofp[s]]) : zero;
        bp[s] = hpost[s] ? __ldg(&f4[obp[s]]) : zero;
    }

    // ---- compute + streaming stores (evict-first: protect L2 read reuse) ----
    #pragma unroll
    for (int s = 0; s < NSP; s++) {
        float4* __restrict__ o =
            reinterpret_cast<float4*>(out) + (size_t)(span0 + s) * (4 * H4);

        float4 r0 = make_float4(fe[s].x - fp[s].x, fe[s].y - fp[s].y,
                                fe[s].z - fp[s].z, fe[s].w - fp[s].w);
        float4 r1 = make_float4(bs[s].x - bp[s].x, bs[s].y - bp[s].y,
                                bs[s].z - bp[s].z, bs[s].w - bp[s].w);

        __stcs(o + t,          r0);     // f_end - f_pre
        __stcs(o + H4 + t,     r1);     // b_start - b_post
        __stcs(o + 2 * H4 + t, fp[s]);  // f_pre
        __stcs(o + 3 * H4 + t, bp[s]);  // b_post
    }
}

extern "C" void kernel_launch(void* const* d_in, const int* in_sizes, int n_in,
                              void* d_out, int out_size)
{
    // Select inputs by element count, immune to ordering:
    // input: B*T*D = 33,554,432 elements; span_idxs: 8,192.
    int big   = (in_sizes[0] >= in_sizes[1]) ? 0 : 1;
    int small = 1 - big;

    const float*        inp  = (const float*)d_in[big];
    const unsigned int* idxs = (const unsigned int*)d_in[small];
    float*              out  = (float*)d_out;

    minus_span_kernel<<<NSPAN_TOT / NSP, 128>>>(inp, idxs, out);
}

// round 9
// speedup vs baseline: 1.0201x; 1.0201x over previous
#include <cuda_runtime.h>
#include <stdint.h>

// MinusSpan: B=16, T=2048, D=1024 (H=512), N_SPANS=256
// out[b,s] = concat(fwd[j]-f_pre, bwd[i]-b_post, f_pre, b_post), zeroed if i==0&&j==0
// Bulk-async (TMA-path) gather version: loads ride the DMA engines, not warps.

static constexpr int Bc = 16;
static constexpr int Tc = 2048;
static constexpr int Dc = 1024;
static constexpr int NS = 256;
static constexpr int D4 = Dc / 4;           // 256 float4 per (b,t) row
static constexpr int H4 = Dc / 8;           // 128 float4 per half-row
static constexpr int NSPAN_TOT = Bc * NS;   // 4096 spans
static constexpr int NSP = 4;               // spans per CTA
static constexpr int REGION_BYTES = 2048;   // one half-row = 512 floats = 2KB

__device__ __forceinline__ uint32_t smem_u32(const void* p) {
    return (uint32_t)__cvta_generic_to_shared(p);
}
__device__ __forceinline__ void mbar_init(uint32_t mbar, uint32_t count) {
    asm volatile("mbarrier.init.shared.b64 [%0], %1;" :: "r"(mbar), "r"(count) : "memory");
}
__device__ __forceinline__ void mbar_expect_tx(uint32_t mbar, uint32_t bytes) {
    asm volatile("mbarrier.arrive.expect_tx.shared.b64 _, [%0], %1;"
                 :: "r"(mbar), "r"(bytes) : "memory");
}
__device__ __forceinline__ void bulk_g2s(uint32_t dst, const void* src,
                                         uint32_t bytes, uint32_t mbar) {
    asm volatile("cp.async.bulk.shared::cluster.global.mbarrier::complete_tx::bytes "
                 "[%0], [%1], %2, [%3];"
                 :: "r"(dst), "l"(src), "r"(bytes), "r"(mbar) : "memory");
}
__device__ __forceinline__ void mbar_wait(uint32_t mbar, uint32_t parity) {
    asm volatile(
        "{\n\t"
        ".reg .pred P1;\n\t"
        "WAIT_LOOP_%=:\n\t"
        "mbarrier.try_wait.parity.acquire.cta.shared::cta.b64 P1, [%0], %1, 0x989680;\n\t"
        "@P1 bra.uni WAIT_DONE_%=;\n\t"
        "bra.uni WAIT_LOOP_%=;\n\t"
        "WAIT_DONE_%=:\n\t"
        "}"
        :: "r"(mbar), "r"(parity) : "memory");
}

__global__ __launch_bounds__(128)
void minus_span_kernel(const float* __restrict__ inp,
                       const unsigned int* __restrict__ idxw,  // raw 32-bit view of span_idxs
                       float* __restrict__ out)
{
    // Stage buffers: [span][region][128 float4]  (region: fe, bs, fp, bp)
    __shared__ alignas(128) float4 stage[NSP][4][H4];
    __shared__ alignas(8) unsigned long long mbar_storage[NSP];
    __shared__ int sh_flags[NSP];   // bit0 skip, bit1 hpre, bit2 hpost

    const int t    = threadIdx.x;           // 0..127
    const int lane = t & 31;
    const int span0 = blockIdx.x * NSP;

    // ---- index-dtype detection (warp 0, broadcast via ballot) ----
    // int64 buffer (vals < 2048, LE): every odd 32-bit word is zero high half.
    // int32: odd words are random j in [0,2048) -> P(all 64 zero) ~ 0.
    bool is64 = false;
    if (t < 32) {
        unsigned w0 = __ldg(&idxw[2 * lane + 1]);
        unsigned w1 = __ldg(&idxw[2 * (lane + 32) + 1]);
        is64 = (__ballot_sync(0xffffffffu, (w0 | w1) != 0u) == 0u);
    }

    if (t == 0) {
        #pragma unroll
        for (int s = 0; s < NSP; s++)
            mbar_init(smem_u32(&mbar_storage[s]), 1);
    }
    __syncthreads();   // barriers + visibility of init before any expect/wait

    // ---- producers: lanes 0..NSP-1 of warp 0 issue all bulk loads ----
    if (t < NSP) {
        const int span = span0 + t;
        const int b    = span >> 8;

        int i, j;
        if (is64) {
            i = (int)__ldg(&idxw[4 * span + 0]);
            j = (int)__ldg(&idxw[4 * span + 2]);
        } else {
            i = (int)__ldg(&idxw[2 * span + 0]);
            j = (int)__ldg(&idxw[2 * span + 1]);
        }

        const bool skip  = (i == 0) && (j == 0);
        const bool hpre  = !skip && (i >= 1);
        const bool hpost = !skip && (j + 1 < Tc);
        sh_flags[t] = (skip ? 1 : 0) | (hpre ? 2 : 0) | (hpost ? 4 : 0);

        // clamp: garbage indices -> wrong values, never faults
        int ic = min(max(i, 0), Tc - 1);
        int jc = min(max(j, 0), Tc - 1);
        int ip = (ic >= 1) ? ic - 1 : 0;
        int jn = (jc + 1 < Tc) ? jc + 1 : Tc - 1;

        const float* base = inp + (size_t)b * Tc * Dc;
        const uint32_t mbar = smem_u32(&mbar_storage[t]);

        uint32_t bytes = (skip ? 0u : 2u * REGION_BYTES)
                       + (hpre ? REGION_BYTES : 0u)
                       + (hpost ? REGION_BYTES : 0u);
        mbar_expect_tx(mbar, bytes);   // tx=0 => barrier flips immediately

        if (!skip) {
            bulk_g2s(smem_u32(&stage[t][0][0]), base + (size_t)jc * Dc,            REGION_BYTES, mbar);
            bulk_g2s(smem_u32(&stage[t][1][0]), base + (size_t)ic * Dc + Dc / 2,   REGION_BYTES, mbar);
        }
        if (hpre)
            bulk_g2s(smem_u32(&stage[t][2][0]), base + (size_t)ip * Dc,            REGION_BYTES, mbar);
        if (hpost)
            bulk_g2s(smem_u32(&stage[t][3][0]), base + (size_t)jn * Dc + Dc / 2,   REGION_BYTES, mbar);
    }
    __syncthreads();   // sh_flags visible to all consumers

    const float4 zero = make_float4(0.f, 0.f, 0.f, 0.f);

    // ---- consumers: all 128 threads sweep spans; later spans land while
    //      earlier ones are computed (natural pipeline) ----
    #pragma unroll
    for (int s = 0; s < NSP; s++) {
        mbar_wait(smem_u32(&mbar_storage[s]), 0);

        const int flags = sh_flags[s];
        const bool skip  = flags & 1;
        const bool hpre  = flags & 2;
        const bool hpost = flags & 4;

        float4 fe = skip  ? zero : stage[s][0][t];
        float4 bs = skip  ? zero : stage[s][1][t];
        float4 fp = hpre  ? stage[s][2][t] : zero;
        float4 bp = hpost ? stage[s][3][t] : zero;

        float4 r0 = make_float4(fe.x - fp.x, fe.y - fp.y, fe.z - fp.z, fe.w - fp.w);
        float4 r1 = make_float4(bs.x - bp.x, bs.y - bp.y, bs.z - bp.z, bs.w - bp.w);

        float4* __restrict__ o =
            reinterpret_cast<float4*>(out) + (size_t)(span0 + s) * (4 * H4);
        __stcs(o + t,          r0);   // f_end - f_pre
        __stcs(o + H4 + t,     r1);   // b_start - b_post
        __stcs(o + 2 * H4 + t, fp);   // f_pre
        __stcs(o + 3 * H4 + t, bp);   // b_post
    }
}

extern "C" void kernel_launch(void* const* d_in, const int* in_sizes, int n_in,
                              void* d_out, int out_size)
{
    // Select inputs by element count, immune to ordering:
    // input: B*T*D = 33,554,432 elements; span_idxs: 8,192.
    int big   = (in_sizes[0] >= in_sizes[1]) ? 0 : 1;
    int small = 1 - big;

    const float*        inp  = (const float*)d_in[big];
    const unsigned int* idxs = (const unsigned int*)d_in[small];
    float*              out  = (float*)d_out;

    minus_span_kernel<<<NSPAN_TOT / NSP, 128>>>(inp, idxs, out);
}

// round 11
// speedup vs baseline: 1.2149x; 1.1910x over previous
#include <cuda_runtime.h>
#include <stdint.h>

// MinusSpan: B=16, T=2048, D=1024 (H=512), N_SPANS=256
// out[b,s] = concat(fwd[j]-f_pre, bwd[i]-b_post, f_pre, b_post), zeroed if i==0&&j==0
// f_pre = fwd[i-1] if i>=1 else 0 ; b_post = bwd[j+1] if j+1<T else 0
//
// R11: re-run of the R10 experiment (R10 died to a 120s harness timeout that a
// store-policy change cannot plausibly cause — treating as infra flake).
// Identical to the R5 winner EXCEPT stores are plain write-back instead of
// __stcs: output is rewritten every graph replay and never read, so keeping it
// L2-resident should collapse the 33.5MB/replay DRAM write stream.

static constexpr int Bc = 16;
static constexpr int Tc = 2048;
static constexpr int Dc = 1024;
static constexpr int NS = 256;
static constexpr int D4 = Dc / 4;           // 256 float4 per (b,t) row
static constexpr int H4 = Dc / 8;           // 128 float4 per half-row
static constexpr int NSPAN_TOT = Bc * NS;   // 4096 spans
static constexpr int NSP = 2;               // spans per CTA (MLP 8 / thread)

__global__ __launch_bounds__(128)
void minus_span_kernel(const float* __restrict__ inp,
                       const unsigned int* __restrict__ idxw,  // raw 32-bit view of span_idxs
                       float* __restrict__ out)
{
    const int t    = threadIdx.x;           // 0..127 (one float4 per region)
    const int lane = t & 31;

    // ---- per-warp index-dtype detection (no extra kernel launch) ----
    // int64 buffer (values < 2048, little-endian): every odd 32-bit word is a
    // zero high half. int32 buffer: odd words are random j in [0,2048) —
    // P(all 64 samples zero) ~ 0. Both layouts have >= 8192 words.
    unsigned w0 = __ldg(&idxw[2 * lane + 1]);
    unsigned w1 = __ldg(&idxw[2 * (lane + 32) + 1]);
    const bool is64 = (__ballot_sync(0xffffffffu, (w0 | w1) != 0u) == 0u);

    const int span0 = blockIdx.x * NSP;
    const float4* __restrict__ f4 = reinterpret_cast<const float4*>(inp);
    float4* __restrict__ o4 = reinterpret_cast<float4*>(out);
    const float4 zero = make_float4(0.f, 0.f, 0.f, 0.f);

    // Per-span state: 32-bit element offsets (max offset 8.4M < 2^31)
    unsigned ofe[NSP], obs[NSP], ofp[NSP], obp[NSP], oout[NSP];
    bool skip[NSP], hpre[NSP], hpost[NSP];

    #pragma unroll
    for (int s = 0; s < NSP; s++) {
        const int span = span0 + s;
        const int b    = span >> 8;         // span / NS

        // Index values fit in the low 32-bit word under both layouts.
        int i, j;
        if (is64) {
            i = (int)idxw[4 * span + 0];
            j = (int)idxw[4 * span + 2];
        } else {
            i = (int)idxw[2 * span + 0];
            j = (int)idxw[2 * span + 1];
        }

        skip[s]  = (i == 0) && (j == 0);
        hpre[s]  = !skip[s] && (i >= 1);
        hpost[s] = !skip[s] && (j + 1 < Tc);

        // Safety clamp: garbage indices become wrong values, never faults.
        int ic = min(max(i, 0), Tc - 1);
        int jc = min(max(j, 0), Tc - 1);
        int ip = (ic >= 1) ? ic - 1 : 0;
        int jn = (jc + 1 < Tc) ? jc + 1 : Tc - 1;

        const unsigned base = (unsigned)b * (Tc * D4);
        ofe[s]  = base + (unsigned)jc * D4 + t;        // fwd[j]
        obs[s]  = base + (unsigned)ic * D4 + H4 + t;   // bwd[i]
        ofp[s]  = base + (unsigned)ip * D4 + t;        // fwd[i-1]
        obp[s]  = base + (unsigned)jn * D4 + H4 + t;   // bwd[j+1]
        oout[s] = (unsigned)span * (4 * H4) + t;       // output row base + t
    }

    // ---- batch all 8 independent LDG.128s before any compute/store ----
    float4 fe[NSP], bs[NSP], fp[NSP], bp[NSP];
    #pragma unroll
    for (int s = 0; s < NSP; s++) {
        fe[s] = skip[s]  ? zero : __ldg(&f4[ofe[s]]);
        bs[s] = skip[s]  ? zero : __ldg(&f4[obs[s]]);
        fp[s] = hpre[s]  ? __ldg(&f4[ofp[s]]) : zero;
        bp[s] = hpost[s] ? __ldg(&f4[obp[s]]) : zero;
    }

    // ---- compute + PLAIN write-back stores (keep output L2-resident across
    //      graph replays; DRAM then carries only cold read misses) ----
    #pragma unroll
    for (int s = 0; s < NSP; s++) {
        float4 r0 = make_float4(fe[s].x - fp[s].x, fe[s].y - fp[s].y,
                                fe[s].z - fp[s].z, fe[s].w - fp[s].w);
        float4 r1 = make_float4(bs[s].x - bp[s].x, bs[s].y - bp[s].y,
                                bs[s].z - bp[s].z, bs[s].w - bp[s].w);

        o4[oout[s]]          = r0;      // f_end - f_pre
        o4[oout[s] + H4]     = r1;      // b_start - b_post
        o4[oout[s] + 2 * H4] = fp[s];   // f_pre
        o4[oout[s] + 3 * H4] = bp[s];   // b_post
    }
}

extern "C" void kernel_launch(void* const* d_in, const int* in_sizes, int n_in,
                              void* d_out, int out_size)
{
    // Select inputs by element count, immune to ordering:
    // input: B*T*D = 33,554,432 elements; span_idxs: 8,192.
    int big   = (in_sizes[0] >= in_sizes[1]) ? 0 : 1;
    int small = 1 - big;

    const float*        inp  = (const float*)d_in[big];
    const unsigned int* idxs = (const unsigned int*)d_in[small];
    float*              out  = (float*)d_out;

    minus_span_kernel<<<NSPAN_TOT / NSP, 128>>>(inp, idxs, out);
}